// round 1
// baseline (speedup 1.0000x reference)
#include <cuda_runtime.h>

#define BATCH 32
#define NPTS  131072
#define NSL   6
#define HW    65536                    // 256*256
#define OUTN  (BATCH * NSL * HW)       // 12,582,912 floats

// -------- scratch: per-batch z min/max as order-preserving uint keys --------
__device__ unsigned g_minkey[BATCH];
__device__ unsigned g_maxkey[BATCH];

__device__ __forceinline__ unsigned f2key(float f) {
    unsigned b = __float_as_uint(f);
    return (b & 0x80000000u) ? ~b : (b | 0x80000000u);
}
__device__ __forceinline__ float key2f(unsigned k) {
    unsigned b = (k & 0x80000000u) ? (k ^ 0x80000000u) : ~k;
    return __uint_as_float(b);
}

// alphas = jnp.linspace(0,1,7) in fp32: alpha[i] = i * fp32(1/6), rounded RN.
// i=5 -> 0x3F555556 (0.8333333730), i=6 -> exactly 1.0f.
__constant__ unsigned c_alpha_bits[7] = {
    0x00000000u, 0x3E2AAAABu, 0x3EAAAAABu, 0x3F000000u,
    0x3F2AAAABu, 0x3F555556u, 0x3F800000u
};

// ---------------- kernel 0: zero output + init min/max sentinels -----------
__global__ void k_init(float* __restrict__ out) {
    int tid = blockIdx.x * blockDim.x + threadIdx.x;
    if (tid < BATCH) { g_minkey[tid] = 0xFFFFFFFFu; g_maxkey[tid] = 0u; }
    int stride = gridDim.x * blockDim.x;
    float4 z4 = make_float4(0.f, 0.f, 0.f, 0.f);
    float4* o4 = (float4*)out;
    for (int i = tid; i < OUTN / 4; i += stride) o4[i] = z4;
}

// ---------------- kernel 1: per-batch z min/max -----------------------------
__global__ void k_minmax(const float* __restrict__ xyz) {
    const int CH = 8, PER = NPTS / CH;      // 8 blocks per batch, 16384 pts each
    int b = blockIdx.x >> 3;
    int c = blockIdx.x & 7;
    long base = (long)b * NPTS + (long)c * PER;
    float mn = 3.4e38f, mx = -3.4e38f;
    for (int i = threadIdx.x; i < PER; i += blockDim.x) {
        float z = __ldg(xyz + (base + i) * 3 + 2);
        mn = fminf(mn, z);
        mx = fmaxf(mx, z);
    }
    #pragma unroll
    for (int o = 16; o > 0; o >>= 1) {
        mn = fminf(mn, __shfl_xor_sync(0xFFFFFFFFu, mn, o));
        mx = fmaxf(mx, __shfl_xor_sync(0xFFFFFFFFu, mx, o));
    }
    __shared__ float smn[8], smx[8];
    int w = threadIdx.x >> 5, l = threadIdx.x & 31;
    if (l == 0) { smn[w] = mn; smx[w] = mx; }
    __syncthreads();
    if (threadIdx.x == 0) {
        int nw = blockDim.x >> 5;
        for (int i = 1; i < nw; i++) { mn = fminf(mn, smn[i]); mx = fmaxf(mx, smx[i]); }
        atomicMin(&g_minkey[b], f2key(mn));
        atomicMax(&g_maxkey[b], f2key(mx));
    }
}

// ---------------- kernel 2: classify + scatter-add histogram ----------------
// 1024 points per block -> exactly 128 blocks per batch, so b is block-constant.
__global__ void k_scatter(const float* __restrict__ xyz, float* __restrict__ out) {
    __shared__ float s_edge[7];
    int b = blockIdx.x >> 7;
    if (threadIdx.x < 7) {
        float zmin = key2f(g_minkey[b]);
        float zmax = key2f(g_maxkey[b]);
        float dz   = __fsub_rn(zmax, zmin);
        float a    = __uint_as_float(c_alpha_bits[threadIdx.x]);
        // edges[s] = zmin + dz * alpha[s], separate mul then add (matches XLA)
        s_edge[threadIdx.x] = __fadd_rn(zmin, __fmul_rn(dz, a));
    }
    __syncthreads();

    long pbase = (long)blockIdx.x * 1024 + threadIdx.x;
    float* obase = out + (long)b * (NSL * HW);

    #pragma unroll
    for (int k = 0; k < 4; k++) {
        long p = pbase + (long)k * 256;
        const float* q = xyz + p * 3;
        float x = __ldg(q);
        float y = __ldg(q + 1);
        float z = __ldg(q + 2);

        // gx = (x - X_MIN) / (X_MAX - X_MIN + EPS) * (W - 1), all fp32 RN,
        // no FMA contraction so it bit-matches the reference lowering.
        float gx = __fmul_rn(__fdiv_rn(__fadd_rn(x, 1.0f), 2.000001f), 255.0f);
        float gy = __fmul_rn(__fdiv_rn(__fadd_rn(y, 1.0f), 2.000001f), 255.0f);

        bool valid = (gy >= 0.0f) && (gy < 256.0f) && (gx >= 0.0f) && (gx < 256.0f);

        int sl = -1;
        #pragma unroll
        for (int s = 0; s < NSL; s++) {
            if (z >= s_edge[s] && z < s_edge[s + 1]) sl = s;
        }

        if (valid && sl >= 0) {
            int iy = min((int)gy, 255);   // gy >= 0 guaranteed by valid
            int ix = min((int)gx, 255);
            atomicAdd(obase + ((sl * 256 + iy) * 256 + ix), 1.0f);
        }
    }
}

// ---------------- kernel 3: log1p + per-(b,s) min/max normalize -------------
__global__ void k_norm(float* __restrict__ out) {
    float* p = out + (long)blockIdx.x * HW;    // one (b,s) plane per block
    float mn = 3.4e38f, mx = -3.4e38f;
    for (int i = threadIdx.x; i < HW; i += blockDim.x) {
        float v = log1pf(p[i]);
        mn = fminf(mn, v);
        mx = fmaxf(mx, v);
    }
    #pragma unroll
    for (int o = 16; o > 0; o >>= 1) {
        mn = fminf(mn, __shfl_xor_sync(0xFFFFFFFFu, mn, o));
        mx = fmaxf(mx, __shfl_xor_sync(0xFFFFFFFFu, mx, o));
    }
    __shared__ float smn[16], smx[16];
    __shared__ float fmn, fmx;
    int w = threadIdx.x >> 5, l = threadIdx.x & 31;
    if (l == 0) { smn[w] = mn; smx[w] = mx; }
    __syncthreads();
    if (threadIdx.x == 0) {
        int nw = blockDim.x >> 5;
        for (int i = 1; i < nw; i++) { mn = fminf(mn, smn[i]); mx = fmaxf(mx, smx[i]); }
        fmn = mn; fmx = mx;
    }
    __syncthreads();
    float m = fmn;
    float d = __fadd_rn(__fsub_rn(fmx, fmn), 1e-6f);
    for (int i = threadIdx.x; i < HW; i += blockDim.x) {
        float v = log1pf(p[i]);
        p[i] = __fdiv_rn(__fsub_rn(v, m), d);
    }
}

// ---------------- launch ----------------------------------------------------
extern "C" void kernel_launch(void* const* d_in, const int* in_sizes, int n_in,
                              void* d_out, int out_size) {
    const float* xyz = (const float*)d_in[0];
    float* out = (float*)d_out;

    k_init   <<<512, 256>>>(out);
    k_minmax <<<256, 256>>>(xyz);            // 32 batches x 8 blocks
    k_scatter<<<(BATCH * NPTS) / 1024, 256>>>(xyz, out);  // 4096 blocks
    k_norm   <<<BATCH * NSL, 512>>>(out);    // 192 blocks, one (b,s) plane each
}

// round 10
// speedup vs baseline: 2.0262x; 2.0262x over previous
#include <cuda_runtime.h>

#define BATCH 32
#define NPTS  131072
#define NSL   6
#define HW    65536                    // 256*256
#define NPLANE (BATCH * NSL)           // 192
#define OUTN  (NPLANE * HW)            // 12,582,912 floats

// -------- scratch: order-preserving uint keys for float min/max --------
__device__ unsigned g_minkey[BATCH];
__device__ unsigned g_maxkey[BATCH];
__device__ unsigned g_pmin[NPLANE];
__device__ unsigned g_pmax[NPLANE];

__device__ __forceinline__ unsigned f2key(float f) {
    unsigned b = __float_as_uint(f);
    return (b & 0x80000000u) ? ~b : (b | 0x80000000u);
}
__device__ __forceinline__ float key2f(unsigned k) {
    unsigned b = (k & 0x80000000u) ? (k ^ 0x80000000u) : ~k;
    return __uint_as_float(b);
}

// alphas = jnp.linspace(0,1,7) in fp32: alpha[i] = RN(i * fp32(1/6)).
__constant__ unsigned c_alpha_bits[7] = {
    0x00000000u, 0x3E2AAAABu, 0x3EAAAAABu, 0x3F000000u,
    0x3F2AAAABu, 0x3F555556u, 0x3F800000u
};

// ---------------- kernel 0: zero output + init sentinels --------------------
__global__ void k_init(float* __restrict__ out) {
    int tid = blockIdx.x * blockDim.x + threadIdx.x;
    if (tid < BATCH) { g_minkey[tid] = 0xFFFFFFFFu; g_maxkey[tid] = 0u; }
    if (tid < NPLANE) { g_pmin[tid] = 0xFFFFFFFFu; g_pmax[tid] = 0u; }
    int stride = gridDim.x * blockDim.x;
    float4 z4 = make_float4(0.f, 0.f, 0.f, 0.f);
    float4* o4 = (float4*)out;
    for (int i = tid; i < OUTN / 4; i += stride) o4[i] = z4;
}

// ---------------- kernel 1: per-batch z min/max (vectorized) ----------------
// Groups of 12 floats (3 float4) hold 4 points; z at lane offsets 2,5,8,11.
__global__ void k_minmax(const float* __restrict__ xyz) {
    int b = blockIdx.x >> 3;               // 8 blocks per batch
    int c = blockIdx.x & 7;
    const int GROUPS = NPTS / 4 / 8;       // 4096 groups of 4 points per block
    const float4* base = (const float4*)(xyz + (long)b * NPTS * 3) + (long)c * GROUPS * 3;
    float mn = 3.4e38f, mx = -3.4e38f;
    for (int g = threadIdx.x; g < GROUPS; g += blockDim.x) {
        float4 a0 = __ldg(base + g * 3 + 0);
        float4 a1 = __ldg(base + g * 3 + 1);
        float4 a2 = __ldg(base + g * 3 + 2);
        mn = fminf(mn, fminf(fminf(a0.z, a1.y), fminf(a2.x, a2.w)));
        mx = fmaxf(mx, fmaxf(fmaxf(a0.z, a1.y), fmaxf(a2.x, a2.w)));
    }
    #pragma unroll
    for (int o = 16; o > 0; o >>= 1) {
        mn = fminf(mn, __shfl_xor_sync(0xFFFFFFFFu, mn, o));
        mx = fmaxf(mx, __shfl_xor_sync(0xFFFFFFFFu, mx, o));
    }
    __shared__ float smn[8], smx[8];
    int w = threadIdx.x >> 5, l = threadIdx.x & 31;
    if (l == 0) { smn[w] = mn; smx[w] = mx; }
    __syncthreads();
    if (threadIdx.x == 0) {
        int nw = blockDim.x >> 5;
        for (int i = 1; i < nw; i++) { mn = fminf(mn, smn[i]); mx = fmaxf(mx, smx[i]); }
        atomicMin(&g_minkey[b], f2key(mn));
        atomicMax(&g_maxkey[b], f2key(mx));
    }
}

// ---------------- kernel 2: classify + scatter-add histogram ----------------
// 1024 points per block -> 128 blocks per batch, b is block-constant.
// Loads vectorized: 4 points = 3 float4 per thread.
__global__ void k_scatter(const float* __restrict__ xyz, float* __restrict__ out) {
    __shared__ float s_edge[7];
    int b = blockIdx.x >> 7;
    if (threadIdx.x < 7) {
        float zmin = key2f(g_minkey[b]);
        float zmax = key2f(g_maxkey[b]);
        float dz   = __fsub_rn(zmax, zmin);
        float a    = __uint_as_float(c_alpha_bits[threadIdx.x]);
        s_edge[threadIdx.x] = __fadd_rn(zmin, __fmul_rn(dz, a));
    }
    __syncthreads();

    const float4* base = (const float4*)(xyz + (long)blockIdx.x * 1024 * 3);
    float* obase = out + (long)b * (NSL * HW);

    int g = threadIdx.x;                       // one group of 4 points per thread
    float4 a0 = __ldg(base + g * 3 + 0);
    float4 a1 = __ldg(base + g * 3 + 1);
    float4 a2 = __ldg(base + g * 3 + 2);
    float px[4] = {a0.x, a0.w, a1.z, a2.y};
    float py[4] = {a0.y, a1.x, a1.w, a2.z};
    float pz[4] = {a0.z, a1.y, a2.x, a2.w};

    #pragma unroll
    for (int k = 0; k < 4; k++) {
        float x = px[k], y = py[k], z = pz[k];
        // (x - X_MIN)/(X_MAX - X_MIN + EPS)*(W-1), fp32 RN, no FMA contraction
        float gx = __fmul_rn(__fdiv_rn(__fadd_rn(x, 1.0f), 2.000001f), 255.0f);
        float gy = __fmul_rn(__fdiv_rn(__fadd_rn(y, 1.0f), 2.000001f), 255.0f);
        bool valid = (gy >= 0.0f) && (gy < 256.0f) && (gx >= 0.0f) && (gx < 256.0f);
        int sl = -1;
        #pragma unroll
        for (int s = 0; s < NSL; s++)
            if (z >= s_edge[s] && z < s_edge[s + 1]) sl = s;
        if (valid && sl >= 0) {
            int iy = min((int)gy, 255);
            int ix = min((int)gx, 255);
            atomicAdd(obase + ((sl * 256 + iy) * 256 + ix), 1.0f);
        }
    }
}

// ------- log1p via shared LUT: counts are small non-negative integers -------
// Exact: lut[i] == log1pf(i) bitwise; fallback covers any count >= 64.
__device__ __forceinline__ float lut_log1p(float c, const float* lut) {
    return (c < 64.0f) ? lut[(int)c] : log1pf(c);
}

// ---------------- kernel 3a: per-plane min/max of log1p(count) --------------
// 8 blocks per plane, 256 threads, 2048 float4 per block chunk.
__global__ void k_norm_reduce(const float* __restrict__ out) {
    __shared__ float lut[64];
    if (threadIdx.x < 64) lut[threadIdx.x] = log1pf((float)threadIdx.x);
    __syncthreads();

    int plane = blockIdx.x >> 3;
    int chunk = blockIdx.x & 7;
    const float4* p = (const float4*)(out + (long)plane * HW + (long)chunk * 8192);
    float mn = 3.4e38f, mx = -3.4e38f;
    for (int i = threadIdx.x; i < 2048; i += blockDim.x) {
        float4 v = __ldg(p + i);
        float l0 = lut_log1p(v.x, lut);
        float l1 = lut_log1p(v.y, lut);
        float l2 = lut_log1p(v.z, lut);
        float l3 = lut_log1p(v.w, lut);
        mn = fminf(mn, fminf(fminf(l0, l1), fminf(l2, l3)));
        mx = fmaxf(mx, fmaxf(fmaxf(l0, l1), fmaxf(l2, l3)));
    }
    #pragma unroll
    for (int o = 16; o > 0; o >>= 1) {
        mn = fminf(mn, __shfl_xor_sync(0xFFFFFFFFu, mn, o));
        mx = fmaxf(mx, __shfl_xor_sync(0xFFFFFFFFu, mx, o));
    }
    __shared__ float smn[8], smx[8];
    int w = threadIdx.x >> 5, l = threadIdx.x & 31;
    if (l == 0) { smn[w] = mn; smx[w] = mx; }
    __syncthreads();
    if (threadIdx.x == 0) {
        for (int i = 1; i < 8; i++) { mn = fminf(mn, smn[i]); mx = fmaxf(mx, smx[i]); }
        atomicMin(&g_pmin[plane], f2key(mn));
        atomicMax(&g_pmax[plane], f2key(mx));
    }
}

// ---------------- kernel 3b: normalize ((log1p - mn) * 1/(mx - mn + eps)) ---
// Reciprocal-multiply instead of per-element divide: ~1 ulp perturbation,
// threshold is 1e-3 and measured rel_err was 3e-8 -> huge headroom.
__global__ void k_norm_apply(float* __restrict__ out) {
    __shared__ float lut[64];
    if (threadIdx.x < 64) lut[threadIdx.x] = log1pf((float)threadIdx.x);
    __syncthreads();

    int plane = blockIdx.x >> 3;
    int chunk = blockIdx.x & 7;
    float m = key2f(g_pmin[plane]);
    float M = key2f(g_pmax[plane]);
    float inv = __fdiv_rn(1.0f, __fadd_rn(__fsub_rn(M, m), 1e-6f));
    float4* p = (float4*)(out + (long)plane * HW + (long)chunk * 8192);
    for (int i = threadIdx.x; i < 2048; i += blockDim.x) {
        float4 v = p[i];
        v.x = __fmul_rn(__fsub_rn(lut_log1p(v.x, lut), m), inv);
        v.y = __fmul_rn(__fsub_rn(lut_log1p(v.y, lut), m), inv);
        v.z = __fmul_rn(__fsub_rn(lut_log1p(v.z, lut), m), inv);
        v.w = __fmul_rn(__fsub_rn(lut_log1p(v.w, lut), m), inv);
        p[i] = v;
    }
}

// ---------------- launch ----------------------------------------------------
extern "C" void kernel_launch(void* const* d_in, const int* in_sizes, int n_in,
                              void* d_out, int out_size) {
    const float* xyz = (const float*)d_in[0];
    float* out = (float*)d_out;

    k_init       <<<1024, 256>>>(out);
    k_minmax     <<<256, 256>>>(xyz);                        // 32 batches x 8 blocks
    k_scatter    <<<(BATCH * NPTS) / 1024, 256>>>(xyz, out); // 4096 blocks
    k_norm_reduce<<<NPLANE * 8, 256>>>(out);                 // 1536 blocks
    k_norm_apply <<<NPLANE * 8, 256>>>(out);                 // 1536 blocks
}